// round 11
// baseline (speedup 1.0000x reference)
#include <cuda_runtime.h>

// NCC loss, 9x9 box, zero pad, win_size=81.
// predict/target: [32,1,512,512] f32 -> scalar f32 = 1 - mean(cross^2/(Ivar*Jvar+1e-6))
//
// f32x2-packed column halves (cols x, x+256). One block = (batch, 57-row strip).
// 288 blocks x 256 threads, 2 blocks/SM, single wave on 144 SMs.
// TWO rows per pipeline stage: one barrier per 2 rows, 2 independent
// tap/reduce streams between barriers (latency hiding via ILP, not just TLP).

typedef unsigned long long u64;

__device__ __forceinline__ u64 pk2(float lo, float hi) {
    u64 r; asm("mov.b64 %0,{%1,%2};" : "=l"(r) : "f"(lo), "f"(hi)); return r;
}
__device__ __forceinline__ void upk2(u64 v, float& lo, float& hi) {
    asm("mov.b64 {%0,%1},%2;" : "=f"(lo), "=f"(hi) : "l"(v));
}
__device__ __forceinline__ u64 add2(u64 a, u64 b) {
    u64 d; asm("add.rn.f32x2 %0,%1,%2;" : "=l"(d) : "l"(a), "l"(b)); return d;
}
__device__ __forceinline__ u64 mul2(u64 a, u64 b) {
    u64 d; asm("mul.rn.f32x2 %0,%1,%2;" : "=l"(d) : "l"(a), "l"(b)); return d;
}
__device__ __forceinline__ u64 fma2(u64 a, u64 b, u64 c) {
    u64 d; asm("fma.rn.f32x2 %0,%1,%2,%3;" : "=l"(d) : "l"(a), "l"(b), "l"(c)); return d;
}

constexpr int W      = 512;
constexpr int H      = 512;
constexpr int HW     = W * H;
constexpr int BATCH  = 32;
constexpr int STRIPS = 9;
constexpr int SROWS  = 57;                  // strips 0..7: 57 rows, strip 8: 56 (masked)
constexpr int NBLK   = BATCH * STRIPS;      // 288
constexpr int TPB    = 256;
constexpr int ITERS  = SROWS + 8;           // 65 row-iterations carry outputs
constexpr int NSTAGE = 33;                  // 2 rows per stage -> 66 row slots
constexpr float INV81 = 1.0f / 81.0f;

// dynamic smem layout
constexpr int SROW_BYTES = 2 * 2 * 264 * 16;          // srow[2][2][264] ulonglong2
constexpr int RING_BYTES = 9 * TPB * 8;               // one u64 ring
constexpr int DSMEM      = SROW_BYTES + 2 * RING_BYTES;  // 16896 + 36864 = 53760

__device__ float g_partials[NBLK];
__device__ unsigned int g_ticket = 0;

struct RowPf { u64 mI, mJ; float hI, hJ; };

__device__ __forceinline__ RowPf load_row(const float* __restrict__ pI,
                                          const float* __restrict__ pJ,
                                          int r, int x) {
    RowPf p; p.mI = 0ull; p.mJ = 0ull; p.hI = 0.f; p.hJ = 0.f;
    if ((unsigned)r < (unsigned)H) {
        const float* ri = pI + r * W;
        const float* rj = pJ + r * W;
        p.mI = pk2(ri[x], ri[x + 256]);
        p.mJ = pk2(rj[x], rj[x + 256]);
        if (x < 8) { p.hI = ri[x + 252]; p.hJ = rj[x + 252]; }
    }
    return p;
}

__device__ __forceinline__ void publish(ulonglong2* __restrict__ dst,
                                        const RowPf& p, int x) {
    ulonglong2 e; e.x = p.mI; e.y = p.mJ;
    dst[4 + x] = e;
    if (x < 8) {
        const bool left = (x < 4);
        ulonglong2 h;
        h.x = left ? pk2(0.f, p.hI) : pk2(p.hI, 0.f);
        h.y = left ? pk2(0.f, p.hJ) : pk2(p.hJ, 0.f);
        dst[left ? x : (256 + x)] = h;
    }
}

__device__ __forceinline__ void row_step(
    const ulonglong2* __restrict__ row, int x, int it, int y0, int k,
    u64 (&rI)[9], u64 (&rJ)[9], u64 (&rJ2)[9],
    u64 (*__restrict__ s_rI2)[TPB], u64 (*__restrict__ s_rIJ)[TPB],
    u64& VI, u64& VJ, u64& VI2, u64& VJ2, u64& VIJ, float& acc)
{
    const u64 NEG1 = pk2(-1.0f, -1.0f);
    const u64 M81  = pk2(-INV81, -INV81);
    const u64 EPS  = pk2(1e-6f, 1e-6f);

    u64 A[9], C[9];
#pragma unroll
    for (int t = 0; t < 9; ++t) {
        const ulonglong2 e = row[x + t];
        A[t] = e.x; C[t] = e.y;
    }
    u64 hI = add2(add2(add2(A[0], A[1]), add2(A[2], A[3])),
                  add2(add2(A[4], A[5]), add2(A[6], A[7])));
    hI = add2(hI, A[8]);
    u64 hJ = add2(add2(add2(C[0], C[1]), add2(C[2], C[3])),
                  add2(add2(C[4], C[5]), add2(C[6], C[7])));
    hJ = add2(hJ, C[8]);
    u64 e0, o0;
    e0 = mul2(A[0], A[0]); e0 = fma2(A[2], A[2], e0); e0 = fma2(A[4], A[4], e0);
    e0 = fma2(A[6], A[6], e0); e0 = fma2(A[8], A[8], e0);
    o0 = mul2(A[1], A[1]); o0 = fma2(A[3], A[3], o0); o0 = fma2(A[5], A[5], o0);
    o0 = fma2(A[7], A[7], o0);
    const u64 hI2 = add2(e0, o0);
    e0 = mul2(C[0], C[0]); e0 = fma2(C[2], C[2], e0); e0 = fma2(C[4], C[4], e0);
    e0 = fma2(C[6], C[6], e0); e0 = fma2(C[8], C[8], e0);
    o0 = mul2(C[1], C[1]); o0 = fma2(C[3], C[3], o0); o0 = fma2(C[5], C[5], o0);
    o0 = fma2(C[7], C[7], o0);
    const u64 hJ2 = add2(e0, o0);
    e0 = mul2(A[0], C[0]); e0 = fma2(A[2], C[2], e0); e0 = fma2(A[4], C[4], e0);
    e0 = fma2(A[6], C[6], e0); e0 = fma2(A[8], C[8], e0);
    o0 = mul2(A[1], C[1]); o0 = fma2(A[3], C[3], o0); o0 = fma2(A[5], C[5], o0);
    o0 = fma2(A[7], C[7], o0);
    const u64 hIJ = add2(e0, o0);

    // vertical running 9-window
    VI  = add2(VI,  hI );  VI  = fma2(rI [k], NEG1, VI );  rI [k] = hI;
    VJ  = add2(VJ,  hJ );  VJ  = fma2(rJ [k], NEG1, VJ );  rJ [k] = hJ;
    VJ2 = add2(VJ2, hJ2);  VJ2 = fma2(rJ2[k], NEG1, VJ2);  rJ2[k] = hJ2;
    {   // smem rings: thread-private [k][x] slots, no sync needed
        const u64 oI2 = s_rI2[k][x];
        VI2 = add2(VI2, hI2);  VI2 = fma2(oI2, NEG1, VI2);  s_rI2[k][x] = hI2;
        const u64 oIJ = s_rIJ[k][x];
        VIJ = add2(VIJ, hIJ);  VIJ = fma2(oIJ, NEG1, VIJ);  s_rIJ[k][x] = hIJ;
    }

    if (it >= 8 && it < ITERS && (y0 + it - 8) < H) {
        const u64 tIn   = mul2(VI, M81);
        const u64 tJn   = mul2(VJ, M81);
        const u64 cross = fma2(tIn, VJ, VIJ);
        const u64 Ivar  = fma2(tIn, VI, VI2);
        const u64 Jvar  = fma2(tJn, VJ, VJ2);
        const u64 num   = mul2(cross, cross);
        const u64 den   = fma2(Ivar, Jvar, EPS);
        float n0, n1, d0, d1;
        upk2(num, n0, n1);
        upk2(den, d0, d1);
        acc += __fdividef(n0, d0);
        acc += __fdividef(n1, d1);
    }
}

__global__ void __launch_bounds__(TPB, 2)
ncc_main_kernel(const float* __restrict__ gI, const float* __restrict__ gJ,
                float* __restrict__ out) {
    extern __shared__ unsigned char dsm[];
    ulonglong2 (*srow)[2][264] = (ulonglong2(*)[2][264])dsm;                 // [phase][row][slot]
    u64 (*s_rI2)[TPB] = (u64(*)[TPB])(dsm + SROW_BYTES);                     // [9][TPB]
    u64 (*s_rIJ)[TPB] = (u64(*)[TPB])(dsm + SROW_BYTES + RING_BYTES);       // [9][TPB]
    __shared__ float s_wsum[TPB / 32];
    __shared__ int s_last;

    const int x     = threadIdx.x;
    const int bx    = blockIdx.x;
    const int strip = bx % STRIPS;
    const int batch = bx / STRIPS;
    const int y0    = strip * SROWS;

    const float* pI = gI + (size_t)batch * HW;
    const float* pJ = gJ + (size_t)batch * HW;

    u64 rI[9], rJ[9], rJ2[9];
#pragma unroll
    for (int k = 0; k < 9; ++k) {
        rI[k] = 0ull; rJ[k] = 0ull; rJ2[k] = 0ull;
        s_rI2[k][x] = 0ull; s_rIJ[k][x] = 0ull;
    }
    u64 VI = 0ull, VJ = 0ull, VI2 = 0ull, VJ2 = 0ull, VIJ = 0ull;
    float acc = 0.0f;

    RowPf pf0 = load_row(pI, pJ, y0 - 4, x);
    RowPf pf1 = load_row(pI, pJ, y0 - 3, x);

#pragma unroll 1
    for (int g = 0; g < 4; ++g) {
#pragma unroll
        for (int j = 0; j < 9; ++j) {              // ring slots (2j)%9,(2j+1)%9: period 9
            const int s = g * 9 + j;
            if (s >= NSTAGE) goto reduce;
            const int it0 = 2 * s;
            const int ph  = s & 1;
            const int k0  = (2 * j) % 9;
            const int k1  = (2 * j + 1) % 9;

            publish(&srow[ph][0][0], pf0, x);
            publish(&srow[ph][1][0], pf1, x);
            __syncthreads();

            // prefetch next stage's rows (covered by the 2-row compute below)
            pf0 = load_row(pI, pJ, y0 - 2 + it0, x);
            pf1 = load_row(pI, pJ, y0 - 1 + it0, x);

            row_step(&srow[ph][0][0], x, it0,     y0, k0,
                     rI, rJ, rJ2, s_rI2, s_rIJ, VI, VJ, VI2, VJ2, VIJ, acc);
            row_step(&srow[ph][1][0], x, it0 + 1, y0, k1,
                     rI, rJ, rJ2, s_rI2, s_rIJ, VI, VJ, VI2, VJ2, VIJ, acc);
        }
    }
reduce:
    // deterministic block reduction (8 warps)
#pragma unroll
    for (int o = 16; o > 0; o >>= 1) acc += __shfl_xor_sync(0xffffffffu, acc, o);
    if ((x & 31) == 0) s_wsum[x >> 5] = acc;
    __syncthreads();
    if (x == 0) {
        float v = 0.f;
#pragma unroll
        for (int w = 0; w < TPB / 32; ++w) v += s_wsum[w];
        g_partials[bx] = v;
        __threadfence();
        unsigned t = atomicAdd(&g_ticket, 1u);
        s_last = (t == (unsigned)(NBLK - 1)) ? 1 : 0;
    }
    __syncthreads();

    // last block: fixed-order final sum (deterministic)
    if (s_last) {
        const volatile float* gp = g_partials;
        float v = gp[x];
        if (x < NBLK - 256) v += gp[256 + x];      // 288 partials over 256 threads
#pragma unroll
        for (int o = 16; o > 0; o >>= 1) v += __shfl_xor_sync(0xffffffffu, v, o);
        if ((x & 31) == 0) s_wsum[x >> 5] = v;
        __syncthreads();
        if (x == 0) {
            float ssum = 0.f;
#pragma unroll
            for (int w = 0; w < TPB / 32; ++w) ssum += s_wsum[w];
            out[0] = 1.0f - ssum * (1.0f / 8388608.0f);   // N = 2^23 exact
            g_ticket = 0;                                  // reset for next replay
        }
    }
}

extern "C" void kernel_launch(void* const* d_in, const int* in_sizes, int n_in,
                              void* d_out, int out_size) {
    const float* predict = (const float*)d_in[0];
    const float* target  = (const float*)d_in[1];
    cudaFuncSetAttribute(ncc_main_kernel,
                         cudaFuncAttributeMaxDynamicSharedMemorySize, DSMEM);
    ncc_main_kernel<<<NBLK, TPB, DSMEM>>>(predict, target, (float*)d_out);
}

// round 12
// speedup vs baseline: 1.0484x; 1.0484x over previous
#include <cuda_runtime.h>

// NCC loss, 9x9 box, zero pad, win_size=81.
// predict/target: [32,1,512,512] f32 -> scalar f32 = 1 - mean(cross^2/(Ivar*Jvar+1e-6))
//
// f32x2-packed column halves (cols x, x+256). One block = (batch, 57-row strip).
// 288 blocks x 256 threads, 2 blocks/SM, single wave on 144 SMs.
// TWO rows per pipeline stage: one barrier per 2 rows, 2 independent
// tap/reduce streams between barriers (latency hiding via ILP, not just TLP).

typedef unsigned long long u64;

__device__ __forceinline__ u64 pk2(float lo, float hi) {
    u64 r; asm("mov.b64 %0,{%1,%2};" : "=l"(r) : "f"(lo), "f"(hi)); return r;
}
__device__ __forceinline__ void upk2(u64 v, float& lo, float& hi) {
    asm("mov.b64 {%0,%1},%2;" : "=f"(lo), "=f"(hi) : "l"(v));
}
__device__ __forceinline__ u64 add2(u64 a, u64 b) {
    u64 d; asm("add.rn.f32x2 %0,%1,%2;" : "=l"(d) : "l"(a), "l"(b)); return d;
}
__device__ __forceinline__ u64 mul2(u64 a, u64 b) {
    u64 d; asm("mul.rn.f32x2 %0,%1,%2;" : "=l"(d) : "l"(a), "l"(b)); return d;
}
__device__ __forceinline__ u64 fma2(u64 a, u64 b, u64 c) {
    u64 d; asm("fma.rn.f32x2 %0,%1,%2,%3;" : "=l"(d) : "l"(a), "l"(b), "l"(c)); return d;
}

constexpr int W      = 512;
constexpr int H      = 512;
constexpr int HW     = W * H;
constexpr int BATCH  = 32;
constexpr int STRIPS = 9;
constexpr int SROWS  = 57;                  // strips 0..7: 57 rows, strip 8: 56 (masked)
constexpr int NBLK   = BATCH * STRIPS;      // 288
constexpr int TPB    = 256;
constexpr int ITERS  = SROWS + 8;           // 65 row-iterations carry outputs
constexpr int NSTAGE = 33;                  // 2 rows per stage -> 66 row slots
constexpr float INV81 = 1.0f / 81.0f;

// dynamic smem layout
constexpr int SROW_BYTES = 2 * 2 * 264 * 16;          // srow[2][2][264] ulonglong2
constexpr int RING_BYTES = 9 * TPB * 8;               // one u64 ring
constexpr int DSMEM      = SROW_BYTES + 2 * RING_BYTES;  // 16896 + 36864 = 53760

__device__ float g_partials[NBLK];
__device__ unsigned int g_ticket = 0;

struct RowPf { u64 mI, mJ; float hI, hJ; };

__device__ __forceinline__ RowPf load_row(const float* __restrict__ pI,
                                          const float* __restrict__ pJ,
                                          int r, int x) {
    RowPf p; p.mI = 0ull; p.mJ = 0ull; p.hI = 0.f; p.hJ = 0.f;
    if ((unsigned)r < (unsigned)H) {
        const float* ri = pI + r * W;
        const float* rj = pJ + r * W;
        p.mI = pk2(ri[x], ri[x + 256]);
        p.mJ = pk2(rj[x], rj[x + 256]);
        if (x < 8) { p.hI = ri[x + 252]; p.hJ = rj[x + 252]; }
    }
    return p;
}

__device__ __forceinline__ void publish(ulonglong2* __restrict__ dst,
                                        const RowPf& p, int x) {
    ulonglong2 e; e.x = p.mI; e.y = p.mJ;
    dst[4 + x] = e;
    if (x < 8) {
        const bool left = (x < 4);
        ulonglong2 h;
        h.x = left ? pk2(0.f, p.hI) : pk2(p.hI, 0.f);
        h.y = left ? pk2(0.f, p.hJ) : pk2(p.hJ, 0.f);
        dst[left ? x : (256 + x)] = h;
    }
}

__device__ __forceinline__ void row_step(
    const ulonglong2* __restrict__ row, int x, int it, int y0, int k,
    u64 (&rI)[9], u64 (&rJ)[9], u64 (&rJ2)[9],
    u64 (*__restrict__ s_rI2)[TPB], u64 (*__restrict__ s_rIJ)[TPB],
    u64& VI, u64& VJ, u64& VI2, u64& VJ2, u64& VIJ, float& acc)
{
    const u64 NEG1 = pk2(-1.0f, -1.0f);
    const u64 M81  = pk2(-INV81, -INV81);
    const u64 EPS  = pk2(1e-6f, 1e-6f);

    u64 A[9], C[9];
#pragma unroll
    for (int t = 0; t < 9; ++t) {
        const ulonglong2 e = row[x + t];
        A[t] = e.x; C[t] = e.y;
    }
    u64 hI = add2(add2(add2(A[0], A[1]), add2(A[2], A[3])),
                  add2(add2(A[4], A[5]), add2(A[6], A[7])));
    hI = add2(hI, A[8]);
    u64 hJ = add2(add2(add2(C[0], C[1]), add2(C[2], C[3])),
                  add2(add2(C[4], C[5]), add2(C[6], C[7])));
    hJ = add2(hJ, C[8]);
    u64 e0, o0;
    e0 = mul2(A[0], A[0]); e0 = fma2(A[2], A[2], e0); e0 = fma2(A[4], A[4], e0);
    e0 = fma2(A[6], A[6], e0); e0 = fma2(A[8], A[8], e0);
    o0 = mul2(A[1], A[1]); o0 = fma2(A[3], A[3], o0); o0 = fma2(A[5], A[5], o0);
    o0 = fma2(A[7], A[7], o0);
    const u64 hI2 = add2(e0, o0);
    e0 = mul2(C[0], C[0]); e0 = fma2(C[2], C[2], e0); e0 = fma2(C[4], C[4], e0);
    e0 = fma2(C[6], C[6], e0); e0 = fma2(C[8], C[8], e0);
    o0 = mul2(C[1], C[1]); o0 = fma2(C[3], C[3], o0); o0 = fma2(C[5], C[5], o0);
    o0 = fma2(C[7], C[7], o0);
    const u64 hJ2 = add2(e0, o0);
    e0 = mul2(A[0], C[0]); e0 = fma2(A[2], C[2], e0); e0 = fma2(A[4], C[4], e0);
    e0 = fma2(A[6], C[6], e0); e0 = fma2(A[8], C[8], e0);
    o0 = mul2(A[1], C[1]); o0 = fma2(A[3], C[3], o0); o0 = fma2(A[5], C[5], o0);
    o0 = fma2(A[7], C[7], o0);
    const u64 hIJ = add2(e0, o0);

    // vertical running 9-window
    VI  = add2(VI,  hI );  VI  = fma2(rI [k], NEG1, VI );  rI [k] = hI;
    VJ  = add2(VJ,  hJ );  VJ  = fma2(rJ [k], NEG1, VJ );  rJ [k] = hJ;
    VJ2 = add2(VJ2, hJ2);  VJ2 = fma2(rJ2[k], NEG1, VJ2);  rJ2[k] = hJ2;
    {   // smem rings: thread-private [k][x] slots, no sync needed
        const u64 oI2 = s_rI2[k][x];
        VI2 = add2(VI2, hI2);  VI2 = fma2(oI2, NEG1, VI2);  s_rI2[k][x] = hI2;
        const u64 oIJ = s_rIJ[k][x];
        VIJ = add2(VIJ, hIJ);  VIJ = fma2(oIJ, NEG1, VIJ);  s_rIJ[k][x] = hIJ;
    }

    if (it >= 8 && it < ITERS && (y0 + it - 8) < H) {
        const u64 tIn   = mul2(VI, M81);
        const u64 tJn   = mul2(VJ, M81);
        const u64 cross = fma2(tIn, VJ, VIJ);
        const u64 Ivar  = fma2(tIn, VI, VI2);
        const u64 Jvar  = fma2(tJn, VJ, VJ2);
        const u64 num   = mul2(cross, cross);
        const u64 den   = fma2(Ivar, Jvar, EPS);
        float n0, n1, d0, d1;
        upk2(num, n0, n1);
        upk2(den, d0, d1);
        acc += __fdividef(n0, d0);
        acc += __fdividef(n1, d1);
    }
}

__global__ void __launch_bounds__(TPB, 2)
ncc_main_kernel(const float* __restrict__ gI, const float* __restrict__ gJ,
                float* __restrict__ out) {
    extern __shared__ unsigned char dsm[];
    ulonglong2 (*srow)[2][264] = (ulonglong2(*)[2][264])dsm;                 // [phase][row][slot]
    u64 (*s_rI2)[TPB] = (u64(*)[TPB])(dsm + SROW_BYTES);                     // [9][TPB]
    u64 (*s_rIJ)[TPB] = (u64(*)[TPB])(dsm + SROW_BYTES + RING_BYTES);       // [9][TPB]
    __shared__ float s_wsum[TPB / 32];
    __shared__ int s_last;

    const int x     = threadIdx.x;
    const int bx    = blockIdx.x;
    const int strip = bx % STRIPS;
    const int batch = bx / STRIPS;
    const int y0    = strip * SROWS;

    const float* pI = gI + (size_t)batch * HW;
    const float* pJ = gJ + (size_t)batch * HW;

    u64 rI[9], rJ[9], rJ2[9];
#pragma unroll
    for (int k = 0; k < 9; ++k) {
        rI[k] = 0ull; rJ[k] = 0ull; rJ2[k] = 0ull;
        s_rI2[k][x] = 0ull; s_rIJ[k][x] = 0ull;
    }
    u64 VI = 0ull, VJ = 0ull, VI2 = 0ull, VJ2 = 0ull, VIJ = 0ull;
    float acc = 0.0f;

    RowPf pf0 = load_row(pI, pJ, y0 - 4, x);
    RowPf pf1 = load_row(pI, pJ, y0 - 3, x);

#pragma unroll 1
    for (int g = 0; g < 4; ++g) {
#pragma unroll
        for (int j = 0; j < 9; ++j) {              // ring slots (2j)%9,(2j+1)%9: period 9
            const int s = g * 9 + j;
            if (s >= NSTAGE) goto reduce;
            const int it0 = 2 * s;
            const int ph  = s & 1;
            const int k0  = (2 * j) % 9;
            const int k1  = (2 * j + 1) % 9;

            publish(&srow[ph][0][0], pf0, x);
            publish(&srow[ph][1][0], pf1, x);
            __syncthreads();

            // prefetch next stage's rows (covered by the 2-row compute below)
            pf0 = load_row(pI, pJ, y0 - 2 + it0, x);
            pf1 = load_row(pI, pJ, y0 - 1 + it0, x);

            row_step(&srow[ph][0][0], x, it0,     y0, k0,
                     rI, rJ, rJ2, s_rI2, s_rIJ, VI, VJ, VI2, VJ2, VIJ, acc);
            row_step(&srow[ph][1][0], x, it0 + 1, y0, k1,
                     rI, rJ, rJ2, s_rI2, s_rIJ, VI, VJ, VI2, VJ2, VIJ, acc);
        }
    }
reduce:
    // deterministic block reduction (8 warps)
#pragma unroll
    for (int o = 16; o > 0; o >>= 1) acc += __shfl_xor_sync(0xffffffffu, acc, o);
    if ((x & 31) == 0) s_wsum[x >> 5] = acc;
    __syncthreads();
    if (x == 0) {
        float v = 0.f;
#pragma unroll
        for (int w = 0; w < TPB / 32; ++w) v += s_wsum[w];
        g_partials[bx] = v;
        __threadfence();
        unsigned t = atomicAdd(&g_ticket, 1u);
        s_last = (t == (unsigned)(NBLK - 1)) ? 1 : 0;
    }
    __syncthreads();

    // last block: fixed-order final sum (deterministic)
    if (s_last) {
        const volatile float* gp = g_partials;
        float v = gp[x];
        if (x < NBLK - 256) v += gp[256 + x];      // 288 partials over 256 threads
#pragma unroll
        for (int o = 16; o > 0; o >>= 1) v += __shfl_xor_sync(0xffffffffu, v, o);
        if ((x & 31) == 0) s_wsum[x >> 5] = v;
        __syncthreads();
        if (x == 0) {
            float ssum = 0.f;
#pragma unroll
            for (int w = 0; w < TPB / 32; ++w) ssum += s_wsum[w];
            out[0] = 1.0f - ssum * (1.0f / 8388608.0f);   // N = 2^23 exact
            g_ticket = 0;                                  // reset for next replay
        }
    }
}

extern "C" void kernel_launch(void* const* d_in, const int* in_sizes, int n_in,
                              void* d_out, int out_size) {
    const float* predict = (const float*)d_in[0];
    const float* target  = (const float*)d_in[1];
    cudaFuncSetAttribute(ncc_main_kernel,
                         cudaFuncAttributeMaxDynamicSharedMemorySize, DSMEM);
    ncc_main_kernel<<<NBLK, TPB, DSMEM>>>(predict, target, (float*)d_out);
}